// round 13
// baseline (speedup 1.0000x reference)
#include <cuda_runtime.h>
#include <cstdint>

// BinLinear: out = input @ sign(tanh(weight)), weight_b in {-1,+1}.
// Identity: out[n,o] = S[n] - 2*T[n,o], S[n]=rowsum(input row n),
//           T[n,o]  = sum of x[n,k] over k where weight[k,o] < 0.
// Exact fp32 products; only summation order differs from reference.
//
// R13: ONE launch. blocks 0..511 binarize (weight -> sign mask, cheap
// release: fence over one 4B store + per-block counter). blocks 512..1535
// rowfill: load row + reduce FIRST (overlaps binarize), poll the counter
// (satisfied by the time 64MB of loads retire), acquire, fence-free store
// phase, then inline exact correction of negative-weight columns (none on
// this dataset). Counters reset per call via ONE per-BLOCK atomic (R12's
// regression was 8192 per-WARP contended atomics).
//
// Deadlock safety: binarize blocks are bids 0..511, scheduled first; at
// worst-case 5 blocks/SM x 148 SMs = 740 resident blocks >= 512, so every
// binarize block runs in wave 1 and the rowfill poll always terminates.
//
// Shapes fixed: M=8192, K=2048 (num_ip), N=2048 (num_op).

#define MDIM 8192
#define KDIM 2048
#define NDIM 2048
#define NQ   (NDIM / 4)      // 512 column quads
#define KB   (KDIM / 8)      // 256 k-groups of 8 (32-bit mask words)
#define FULL 0xffffffffu

#define BIN_BLOCKS 512
#define RF_BLOCKS  1024
#define GRID (BIN_BLOCKS + RF_BLOCKS)

// Scratch (no cudaMalloc). Zero-initialized; mask writes value-identical
// across replays, OR-atomics idempotent, counters reset to zero each call
// -> every call does the same work and produces the same output.
// g_mask[kb*NQ + c4]: bit (j*4+e) = sign of weight[kb*8+j][c4*4+e] (1 => -1).
__device__ uint32_t g_mask[KB * NQ];     // 512 KB
__device__ uint32_t g_negq[NQ];          // per-quad OR of mask words (rare path)
__device__ uint32_t g_anyflag;           // nonzero iff any negative weight
__device__ unsigned int g_cnt;           // binarize blocks completed
__device__ unsigned int g_fin;           // rowfill blocks completed

__global__ void __launch_bounds__(256)
mega_kernel(const float4* __restrict__ w4,
            const float* __restrict__ x,
            float* __restrict__ out) {
    int bid = blockIdx.x;

    if (bid < BIN_BLOCKS) {
        // ---- binarize: thread owns (quad c4, 8 k's) ----
        int tid = bid * 256 + threadIdx.x;           // 0..131071
        int c4  = tid & (NQ - 1);                    // fastest -> coalesced
        int kb  = tid >> 9;                          // 0..255
        const float4* base = w4 + (size_t)(kb * 8) * NQ + c4;

        uint32_t bits = 0;
        #pragma unroll
        for (int j = 0; j < 8; j++) {
            float4 v = __ldcs(&base[(size_t)j * NQ]);
            uint32_t b = (uint32_t)(v.x < 0.0f)
                       | ((uint32_t)(v.y < 0.0f) << 1)
                       | ((uint32_t)(v.z < 0.0f) << 2)
                       | ((uint32_t)(v.w < 0.0f) << 3);
            bits |= b << (j * 4);
        }
        g_mask[kb * NQ + c4] = bits;                 // one 4B store in flight

        if (bits) {                                  // rare path (idempotent)
            atomicOr(&g_negq[c4], bits);
            atomicOr(&g_anyflag, 1u);
        }

        // Release: per-thread fence covers its single mask store (cheap);
        // bar chains all fences before the per-block counter add.
        __threadfence();
        __syncthreads();
        if (threadIdx.x == 0) atomicAdd(&g_cnt, 1u);
        return;
    }

    // ---- rowfill: one warp per row ----
    int rb   = bid - BIN_BLOCKS;                     // 0..1023
    int lane = threadIdx.x & 31;
    int row  = rb * 8 + (threadIdx.x >> 5);
    const float4* xrow4 = (const float4*)(x + (size_t)row * KDIM);

    // Load + reduce first: 64MB input stream overlaps binarize's 16MB.
    float s = 0.0f;
    #pragma unroll
    for (int half = 0; half < 2; half++) {           // 2 batches of 8 in flight
        float4 v[8];
        #pragma unroll
        for (int i = 0; i < 8; i++)
            v[i] = __ldcs(&xrow4[lane + 32 * (half * 8 + i)]);
        #pragma unroll
        for (int i = 0; i < 8; i++)
            s += (v[i].x + v[i].y) + (v[i].z + v[i].w);
    }
    #pragma unroll
    for (int ofs = 16; ofs; ofs >>= 1)
        s += __shfl_xor_sync(FULL, s, ofs);          // all lanes hold S

    // Wait for binarize completion (satisfied by now in the common case).
    if (lane == 0)
        while (*(volatile unsigned int*)&g_cnt < BIN_BLOCKS)
            __nanosleep(64);
    __syncwarp();
    __threadfence();                                 // acquire (loads only: cheap)
    uint32_t flag = g_anyflag;

    // Fence-free pure store phase.
    float4* orow4 = (float4*)(out + (size_t)row * NDIM);
    float4 val = make_float4(s, s, s, s);
    #pragma unroll
    for (int i = 0; i < 16; i++)
        orow4[lane + 32 * i] = val;

    // General path (absent on this dataset, kept exact): the SAME thread
    // that stored a quad overwrites its affected elements -> per-thread
    // per-address program order, no fence needed.
    if (flag != 0) {
        const float* xrow = x + (size_t)row * KDIM;
        #pragma unroll 1
        for (int i = 0; i < 16; i++) {
            int c4 = lane + 32 * i;                  // columns c4*4..c4*4+3
            uint32_t q = g_negq[c4];
            if (!q) continue;
            #pragma unroll 1
            for (int e = 0; e < 4; e++) {
                if ((q >> e) & 0x11111111u) {
                    float T = 0.0f;
                    for (int kb = 0; kb < KB; kb++) {
                        uint32_t word = g_mask[kb * NQ + c4];
                        uint32_t sel = (word >> e) & 0x11111111u;
                        while (sel) {
                            int b = __ffs(sel) - 1;  // b = j*4
                            sel &= sel - 1;
                            T += xrow[kb * 8 + (b >> 2)];
                        }
                    }
                    out[(size_t)row * NDIM + c4 * 4 + e] = s - 2.0f * T;
                }
            }
        }
    }

    // Per-BLOCK completion: last rowfill block resets both counters.
    // All rowfill warps passed their polls before fin can reach 1023, and
    // g_cnt is exactly BIN_BLOCKS by then -> race-free reset; state is
    // all-zero at the end of every call (deterministic across replays).
    __syncthreads();
    if (threadIdx.x == 0) {
        if (atomicAdd(&g_fin, 1u) == RF_BLOCKS - 1) {
            g_fin = 0;
            g_cnt = 0;
            __threadfence();
        }
    }
}

extern "C" void kernel_launch(void* const* d_in, const int* in_sizes, int n_in,
                              void* d_out, int out_size) {
    const float* input  = (const float*)d_in[0];   // [8192, 2048]
    const float* weight = (const float*)d_in[1];   // [2048, 2048]
    float* out = (float*)d_out;                    // [8192, 2048]

    mega_kernel<<<GRID, 256>>>((const float4*)weight, input, out);
}

// round 14
// speedup vs baseline: 1.2993x; 1.2993x over previous
#include <cuda_runtime.h>
#include <cstdint>

// BinLinear: out = input @ sign(tanh(weight)), weight_b in {-1,+1}.
// Identity: out[n,o] = S[n] - 2*T[n,o], S[n]=rowsum(input row n),
//           T[n,o]  = sum of x[n,k] over k where weight[k,o] < 0.
// Exact fp32 products; only summation order differs from reference.
//
// R14 = R10's proven two-kernel structure (mega at the ~6.4TB/s LTS cap +
// fixup that fast-exits when no negative weights exist) with the fixup's
// 4.35us of pure launch overhead hidden via Programmatic Dependent Launch:
// fixup is launched with programmaticStreamSerializationAllowed=1 so its
// grid setup overlaps mega's tail; cudaGridDependencySynchronize() at the
// top of fixup guarantees all of mega's stores are visible before the flag
// read / any general-path overwrite. No intra-kernel cross-block sync
// (R11-R13 showed every such variant costs 4-9us on this chip).
//
// Shapes fixed: M=8192, K=2048 (num_ip), N=2048 (num_op).

#define MDIM 8192
#define KDIM 2048
#define NDIM 2048
#define NQ   (NDIM / 4)      // 512 column quads
#define KB   (KDIM / 8)      // 256 k-groups of 8 (32-bit mask words)
#define FULL 0xffffffffu
#define FIX_BLOCKS 64

// Scratch (no cudaMalloc). Zero-initialized; mask writes value-identical
// across replays, OR-atomics idempotent -> replay-deterministic.
// g_mask[kb*NQ + c4]: bit (j*4+e) = sign of weight[kb*8+j][c4*4+e] (1 => -1).
__device__ uint32_t g_mask[KB * NQ];     // 512 KB
__device__ uint32_t g_negq[NQ];          // per-quad OR of mask words (rare path)
__device__ uint32_t g_anyflag;           // nonzero iff any negative weight
__device__ float    g_S[MDIM];           // row sums (read by fixup)

// ---------------------------------------------------------------------------
// Mega kernel (byte-identical hot path to R10's 22.6us version):
// 1536 blocks, roles interleaved 2:1.
//   bid%3 < 2  -> rowfill (8 warps, warp-per-row): 16 evict-first LDG.128 ->
//                 shuffle reduce -> S -> store g_S -> 16 plain STG.128.
//   bid%3 == 2 -> binarize: thread owns (quad c4, 8 k's): 8 evict-first
//                 LDG.128, pack 32 sign bits, 1 word store (+ idempotent
//                 atomics only if negatives exist).
// Each block triggers PDL completion after its last store.
// ---------------------------------------------------------------------------
__global__ void __launch_bounds__(256) mega_kernel(const float4* __restrict__ w4,
                                                   const float* __restrict__ x,
                                                   float* __restrict__ out) {
    int bid = blockIdx.x;
    int g = bid / 3;
    int rem = bid - g * 3;

    if (rem < 2) {
        // ---- rowfill: one-pass read row -> S -> write row ----
        int rb   = g * 2 + rem;                      // 0..1023
        int row  = rb * 8 + (threadIdx.x >> 5);
        int lane = threadIdx.x & 31;
        const float4* xrow4 = (const float4*)(x + (size_t)row * KDIM);

        float s = 0.0f;
        #pragma unroll
        for (int half = 0; half < 2; half++) {       // 2 batches of 8 in flight
            float4 v[8];
            #pragma unroll
            for (int i = 0; i < 8; i++)
                v[i] = __ldcs(&xrow4[lane + 32 * (half * 8 + i)]);
            #pragma unroll
            for (int i = 0; i < 8; i++)
                s += (v[i].x + v[i].y) + (v[i].z + v[i].w);
        }
        #pragma unroll
        for (int ofs = 16; ofs; ofs >>= 1)
            s += __shfl_xor_sync(FULL, s, ofs);      // all lanes hold S
        if (lane == 0) g_S[row] = s;

        float4 val = make_float4(s, s, s, s);
        float4* orow4 = (float4*)(out + (size_t)row * NDIM);
        #pragma unroll
        for (int i = 0; i < 16; i++)
            orow4[lane + 32 * i] = val;              // plain stores -> L2
    } else {
        // ---- binarize: thread owns (c4, 8 k's) ----
        int tid = g * 256 + threadIdx.x;             // 0..131071
        int c4  = tid & (NQ - 1);                    // fastest -> coalesced
        int kb  = tid >> 9;                          // 0..255
        const float4* base = w4 + (size_t)(kb * 8) * NQ + c4;

        uint32_t bits = 0;
        #pragma unroll
        for (int j = 0; j < 8; j++) {
            float4 v = __ldcs(&base[(size_t)j * NQ]);
            uint32_t b = (uint32_t)(v.x < 0.0f)
                       | ((uint32_t)(v.y < 0.0f) << 1)
                       | ((uint32_t)(v.z < 0.0f) << 2)
                       | ((uint32_t)(v.w < 0.0f) << 3);
            bits |= b << (j * 4);
        }
        g_mask[kb * NQ + c4] = bits;                 // coalesced word store

        if (bits) {                                  // rare path (idempotent)
            atomicOr(&g_negq[c4], bits);
            atomicOr(&g_anyflag, 1u);
        }
    }

    // PDL: this block is done writing; allow the dependent grid to launch.
    // (Memory visibility for the consumer is enforced by its
    //  cudaGridDependencySynchronize, which waits for ALL blocks + flush.)
    cudaTriggerProgrammaticLaunchCompletion();
}

// ---------------------------------------------------------------------------
// Fixup (PDL secondary): waits for mega completion + memory flush, then
// fast-exits when no negative weights exist (dataset case). General case:
// strides over column quads; overwrites affected elements with the exact
// S[n] - 2*T[n,c] recomputed from input + mask (pure overwrite, no RMW).
// ---------------------------------------------------------------------------
__global__ void __launch_bounds__(256) fixup_kernel(const float* __restrict__ x,
                                                    float* __restrict__ out) {
    cudaGridDependencySynchronize();                 // mega complete + visible

    if (g_anyflag == 0) return;                      // broadcast, L2-hot

    for (int c4 = blockIdx.x; c4 < NQ; c4 += FIX_BLOCKS) {
        uint32_t q = g_negq[c4];
        if (q == 0) continue;
        for (int n = threadIdx.x; n < MDIM; n += 256) {
            const float* xrow = x + (size_t)n * KDIM;
            float s = g_S[n];
            #pragma unroll
            for (int e = 0; e < 4; e++) {
                if ((q >> e) & 0x11111111u) {
                    float T = 0.0f;
                    for (int kb = 0; kb < KB; kb++) {
                        uint32_t word = g_mask[kb * NQ + c4];
                        uint32_t sel = (word >> e) & 0x11111111u;
                        while (sel) {
                            int b = __ffs(sel) - 1;  // b = j*4
                            sel &= sel - 1;
                            T += xrow[kb * 8 + (b >> 2)];
                        }
                    }
                    out[(size_t)n * NDIM + c4 * 4 + e] = s - 2.0f * T;
                }
            }
        }
    }
}

extern "C" void kernel_launch(void* const* d_in, const int* in_sizes, int n_in,
                              void* d_out, int out_size) {
    const float* input  = (const float*)d_in[0];   // [8192, 2048]
    const float* weight = (const float*)d_in[1];   // [2048, 2048]
    float* out = (float*)d_out;                    // [8192, 2048]

    mega_kernel<<<1536, 256>>>((const float4*)weight, input, out);

    // Fixup with Programmatic Dependent Launch: its launch/ramp overlaps
    // mega's tail instead of serializing after it.
    cudaLaunchConfig_t cfg = {};
    cfg.gridDim  = dim3(FIX_BLOCKS, 1, 1);
    cfg.blockDim = dim3(256, 1, 1);
    cfg.dynamicSmemBytes = 0;
    cudaLaunchAttribute attrs[1];
    attrs[0].id = cudaLaunchAttributeProgrammaticStreamSerialization;
    attrs[0].val.programmaticStreamSerializationAllowed = 1;
    cfg.attrs = attrs;
    cfg.numAttrs = 1;
    cudaLaunchKernelEx(&cfg, fixup_kernel, input, out);
}